// round 3
// baseline (speedup 1.0000x reference)
#include <cuda_runtime.h>
#include <cstdint>
#include <cstddef>

// ---------------------------------------------------------------------------
// PolicyHead round 2:
//   kernel 1: out = relu(x@W1^T+b1)           (pipelined tf32 mma GEMM)
//   kernel 2 (fused, per 64-row block):
//       q = out_b@W2^T+b2 ; k = out_b@W3^T+b3  (in-smem, weights from L2)
//       logits = q@k^T * SCALE ; promo ; gather(1858)
// Removes the 1.07GB q/k global round trip and pipelines all global loads.
// ---------------------------------------------------------------------------

#define HDIM 256
#define MROWS_MAX 262144
#define PSCALE 0.0625f

__device__ float g_out[(size_t)MROWS_MAX * HDIM];

__device__ __forceinline__ unsigned f2tf(float f) {
    unsigned r;
    asm("cvt.rna.tf32.f32 %0, %1;" : "=r"(r) : "f"(f));
    return r;
}

__device__ __forceinline__ void mma8(float* d, const unsigned* a, const unsigned* b) {
    asm volatile(
        "mma.sync.aligned.m16n8k8.row.col.f32.tf32.tf32.f32 "
        "{%0,%1,%2,%3}, {%4,%5,%6,%7}, {%8,%9}, {%0,%1,%2,%3};\n"
        : "+f"(d[0]), "+f"(d[1]), "+f"(d[2]), "+f"(d[3])
        : "r"(a[0]), "r"(a[1]), "r"(a[2]), "r"(a[3]), "r"(b[0]), "r"(b[1]));
}

// ---------------------------------------------------------------------------
// GEMM1: C = relu(A[M,256] @ W[256,256]^T + b). Tile 128x128, 8 warps,
// BK=32, register-staged software pipeline (LDG next chunk during mma).
// ---------------------------------------------------------------------------
__global__ __launch_bounds__(256, 2)
void gemm1_kernel(const float* __restrict__ A, const float* __restrict__ W,
                  const float* __restrict__ bias, float* __restrict__ C) {
    __shared__ unsigned As[128 * 36];
    __shared__ unsigned Bs[128 * 36];
    const int m0 = blockIdx.y * 128;
    const int n0 = blockIdx.x * 128;
    const int tid = threadIdx.x;
    const int warp = tid >> 5, lane = tid & 31;
    const int g = lane >> 2, t = lane & 3;
    const int wm = warp >> 1, wn = warp & 1;

    float acc[2][8][4];
#pragma unroll
    for (int i = 0; i < 2; i++)
#pragma unroll
        for (int j = 0; j < 8; j++)
#pragma unroll
            for (int l = 0; l < 4; l++) acc[i][j][l] = 0.f;

    const int lrow = tid >> 3;
    const int lcol = (tid & 7) * 4;

    float4 ra[4], rb[4];
#pragma unroll
    for (int i = 0; i < 4; i++) {
        int row = lrow + i * 32;
        ra[i] = *(const float4*)(A + (size_t)(m0 + row) * HDIM + lcol);
        rb[i] = *(const float4*)(W + (size_t)(n0 + row) * HDIM + lcol);
    }

    for (int k0 = 0; k0 < HDIM; k0 += 32) {
#pragma unroll
        for (int i = 0; i < 4; i++) {
            int row = lrow + i * 32;
            *(uint4*)&As[row * 36 + lcol] =
                make_uint4(f2tf(ra[i].x), f2tf(ra[i].y), f2tf(ra[i].z), f2tf(ra[i].w));
            *(uint4*)&Bs[row * 36 + lcol] =
                make_uint4(f2tf(rb[i].x), f2tf(rb[i].y), f2tf(rb[i].z), f2tf(rb[i].w));
        }
        __syncthreads();
        if (k0 + 32 < HDIM) {
#pragma unroll
            for (int i = 0; i < 4; i++) {
                int row = lrow + i * 32;
                ra[i] = *(const float4*)(A + (size_t)(m0 + row) * HDIM + k0 + 32 + lcol);
                rb[i] = *(const float4*)(W + (size_t)(n0 + row) * HDIM + k0 + 32 + lcol);
            }
        }
#pragma unroll
        for (int ks = 0; ks < 32; ks += 8) {
            unsigned a[2][4], b[8][2];
#pragma unroll
            for (int mi = 0; mi < 2; mi++) {
                int r = wm * 32 + mi * 16;
                a[mi][0] = As[(r + g) * 36 + ks + t];
                a[mi][1] = As[(r + g + 8) * 36 + ks + t];
                a[mi][2] = As[(r + g) * 36 + ks + t + 4];
                a[mi][3] = As[(r + g + 8) * 36 + ks + t + 4];
            }
#pragma unroll
            for (int ni = 0; ni < 8; ni++) {
                int c = wn * 64 + ni * 8;
                b[ni][0] = Bs[(c + g) * 36 + ks + t];
                b[ni][1] = Bs[(c + g) * 36 + ks + t + 4];
            }
#pragma unroll
            for (int mi = 0; mi < 2; mi++)
#pragma unroll
                for (int ni = 0; ni < 8; ni++)
                    mma8(acc[mi][ni], a[mi], b[ni]);
        }
        __syncthreads();
    }
#pragma unroll
    for (int mi = 0; mi < 2; mi++) {
#pragma unroll
        for (int h = 0; h < 2; h++) {
            int r = m0 + wm * 32 + mi * 16 + g + h * 8;
#pragma unroll
            for (int ni = 0; ni < 8; ni++) {
                int c = n0 + wn * 64 + ni * 8 + 2 * t;
                float v0 = fmaxf(acc[mi][ni][h * 2 + 0] + bias[c], 0.f);
                float v1 = fmaxf(acc[mi][ni][h * 2 + 1] + bias[c + 1], 0.f);
                *(float2*)(C + (size_t)r * HDIM + c) = make_float2(v0, v1);
            }
        }
    }
}

// ---------------------------------------------------------------------------
// Fused kernel. One CTA (256 threads) per 64-row block.
// smem (unsigned words): outs[64*260] | qs[64*260] | ks[64*260] | ws[256*20] | offs[32]
// fulls (4288 floats) aliases outs after q/k are built.
// ---------------------------------------------------------------------------
constexpr int OS = 260;       // stride for outs/qs/ks  (260 % 32 == 4 -> conflict-free)
constexpr int WST = 20;       // ws stride              (20 % 32 == 4)
constexpr int SM_OUTS = 0;
constexpr int SM_QS   = 64 * OS;
constexpr int SM_KS   = 2 * 64 * OS;
constexpr int SM_WS   = 3 * 64 * OS;
constexpr int SM_OFFS = 3 * 64 * OS + 256 * WST;
constexpr int SM_WORDS = SM_OFFS + 32;

// GEMM pass: dst[64,256] = tf32(outs @ W^T + bias). Warp tile 16x128 (4x2 warps).
__device__ __forceinline__ void qk_gemm(const unsigned* __restrict__ outs,
                                        unsigned* __restrict__ ws,
                                        unsigned* __restrict__ dst,
                                        const float* __restrict__ W,
                                        const float* __restrict__ bias,
                                        int tid, int wm, int wn, int g, int t) {
    float acc[16][4];
#pragma unroll
    for (int i = 0; i < 16; i++)
#pragma unroll
        for (int j = 0; j < 4; j++) acc[i][j] = 0.f;

    float4 st[4];
#pragma unroll
    for (int i = 0; i < 4; i++) {
        int j = tid + 256 * i;
        st[i] = *(const float4*)(W + (size_t)(j >> 2) * HDIM + (j & 3) * 4);
    }

    for (int k0 = 0; k0 < HDIM; k0 += 16) {
#pragma unroll
        for (int i = 0; i < 4; i++) {
            int j = tid + 256 * i;
            *(uint4*)&ws[(j >> 2) * WST + (j & 3) * 4] =
                make_uint4(f2tf(st[i].x), f2tf(st[i].y), f2tf(st[i].z), f2tf(st[i].w));
        }
        __syncthreads();
        if (k0 + 16 < HDIM) {
#pragma unroll
            for (int i = 0; i < 4; i++) {
                int j = tid + 256 * i;
                st[i] = *(const float4*)(W + (size_t)(j >> 2) * HDIM + k0 + 16 + (j & 3) * 4);
            }
        }
#pragma unroll
        for (int ks = 0; ks < 16; ks += 8) {
            unsigned a[4];
            int r = wm * 16;
            a[0] = outs[(r + g) * OS + k0 + ks + t];
            a[1] = outs[(r + g + 8) * OS + k0 + ks + t];
            a[2] = outs[(r + g) * OS + k0 + ks + t + 4];
            a[3] = outs[(r + g + 8) * OS + k0 + ks + t + 4];
#pragma unroll
            for (int ni = 0; ni < 16; ni++) {
                unsigned bb[2];
                int c = wn * 128 + ni * 8;
                bb[0] = ws[(c + g) * WST + ks + t];
                bb[1] = ws[(c + g) * WST + ks + t + 4];
                mma8(acc[ni], a, bb);
            }
        }
        __syncthreads();
    }
    // epilogue: bias, tf32, store
#pragma unroll
    for (int ni = 0; ni < 16; ni++) {
        int c = wn * 128 + ni * 8 + 2 * t;
        int r = wm * 16 + g;
        float bc0 = bias[c], bc1 = bias[c + 1];
        dst[r * OS + c]           = f2tf(acc[ni][0] + bc0);
        dst[r * OS + c + 1]       = f2tf(acc[ni][1] + bc1);
        dst[(r + 8) * OS + c]     = f2tf(acc[ni][2] + bc0);
        dst[(r + 8) * OS + c + 1] = f2tf(acc[ni][3] + bc1);
    }
}

__global__ __launch_bounds__(256, 1)
void fused_kernel(const float* __restrict__ Of,
                  const float* __restrict__ w2, const float* __restrict__ b2,
                  const float* __restrict__ w3, const float* __restrict__ b3,
                  const float* __restrict__ w4, const int* __restrict__ gidx,
                  float* __restrict__ out) {
    extern __shared__ unsigned sm[];
    unsigned* outs = sm + SM_OUTS;
    unsigned* qs   = sm + SM_QS;
    unsigned* kss  = sm + SM_KS;
    unsigned* ws   = sm + SM_WS;
    float* offs_sm = (float*)(sm + SM_OFFS);
    float* fulls   = (float*)outs;     // alias: outs dead after q/k built

    const int b = blockIdx.x;
    const int tid = threadIdx.x;
    const float* og = Of + (size_t)b * 64 * HDIM;

    // load out block -> outs (tf32)
    for (int i = tid * 4; i < 64 * HDIM; i += 256 * 4) {
        int row = i >> 8, col = i & 255;
        float4 v = *(const float4*)(og + i);
        *(uint4*)&outs[row * OS + col] =
            make_uint4(f2tf(v.x), f2tf(v.y), f2tf(v.z), f2tf(v.w));
    }
    __syncthreads();

    const int warp = tid >> 5, lane = tid & 31;
    const int g = lane >> 2, t = lane & 3;
    const int wm = warp >> 1, wn = warp & 1;

    qk_gemm(outs, ws, qs,  w2, b2, tid, wm, wn, g, t);
    qk_gemm(outs, ws, kss, w3, b3, tid, wm, wn, g, t);
    __syncthreads();   // q/k visible to all warps

    // ---- logits = q @ k^T * SCALE  (warp tile 16x32, 4x2 warps) ----
    float acc[4][4];
#pragma unroll
    for (int i = 0; i < 4; i++)
#pragma unroll
        for (int j = 0; j < 4; j++) acc[i][j] = 0.f;

    for (int k8 = 0; k8 < HDIM; k8 += 8) {
        unsigned a[4], bb[4][2];
        int r = wm * 16;
        a[0] = qs[(r + g) * OS + k8 + t];
        a[1] = qs[(r + g + 8) * OS + k8 + t];
        a[2] = qs[(r + g) * OS + k8 + t + 4];
        a[3] = qs[(r + g + 8) * OS + k8 + t + 4];
#pragma unroll
        for (int ni = 0; ni < 4; ni++) {
            int c = wn * 32 + ni * 8;
            bb[ni][0] = kss[(c + g) * OS + k8 + t];
            bb[ni][1] = kss[(c + g) * OS + k8 + t + 4];
        }
#pragma unroll
        for (int ni = 0; ni < 4; ni++) mma8(acc[ni], a, bb[ni]);
    }
    __syncthreads();   // everyone done reading outs-alias region? (fulls writes next)
#pragma unroll
    for (int ni = 0; ni < 4; ni++) {
        int c = wn * 32 + ni * 8 + 2 * t;
        int r0 = wm * 16 + g;
        fulls[r0 * 64 + c]           = acc[ni][0] * PSCALE;
        fulls[r0 * 64 + c + 1]       = acc[ni][1] * PSCALE;
        fulls[(r0 + 8) * 64 + c]     = acc[ni][2] * PSCALE;
        fulls[(r0 + 8) * 64 + c + 1] = acc[ni][3] * PSCALE;
    }
    __syncthreads();

    // ---- promo offsets: offs[p][s] = dot(k[56+s], w4[p]) ----
    if (warp == 0) {
        int p = lane >> 3, s = lane & 7;
        const float* w4r = w4 + p * HDIM;
        const unsigned* kr = &kss[(56 + s) * OS];
        float sum = 0.f;
#pragma unroll 8
        for (int hh = 0; hh < HDIM; hh++)
            sum += __uint_as_float(kr[hh]) * w4r[hh];
        offs_sm[lane] = sum;
    }
    __syncthreads();

    if (tid < 192) {
        int qq = tid / 24, rr = tid % 24, s = rr / 3, p = rr % 3;
        fulls[4096 + tid] = offs_sm[p * 8 + s] + offs_sm[24 + s]
                          + fulls[(48 + qq) * 64 + 56 + s];
    }
    __syncthreads();

    // ---- gather ----
    float* ob = out + (size_t)b * 1858;
    for (int i = tid; i < 1858; i += 256) ob[i] = fulls[gidx[i]];
}

// ---------------------------------------------------------------------------
extern "C" void kernel_launch(void* const* d_in, const int* in_sizes, int n_in,
                              void* d_out, int out_size) {
    const float* x  = (const float*)d_in[0];
    const float* w1 = (const float*)d_in[1];
    const float* b1 = (const float*)d_in[2];
    const float* w2 = (const float*)d_in[3];
    const float* b2 = (const float*)d_in[4];
    const float* w3 = (const float*)d_in[5];
    const float* b3 = (const float*)d_in[6];
    const float* w4 = (const float*)d_in[7];
    const int*   gi = (const int*)d_in[8];
    float* out = (float*)d_out;

    const int M = in_sizes[0] / HDIM;     // 262144
    const int nblk = M / 64;              // 4096

    float* o;
    cudaGetSymbolAddress((void**)&o, g_out);

    dim3 gg(HDIM / 128, M / 128);
    gemm1_kernel<<<gg, 256>>>(x, w1, b1, o);

    size_t shmem = (size_t)SM_WORDS * sizeof(unsigned);   // ~220 KB
    static bool attr_set = false;
    if (!attr_set) {
        cudaFuncSetAttribute((const void*)fused_kernel,
                             cudaFuncAttributeMaxDynamicSharedMemorySize, (int)shmem);
        attr_set = true;
    }
    fused_kernel<<<nblk, 256, shmem>>>(o, w2, b2, w3, b3, w4, gi, out);
}

// round 4
// speedup vs baseline: 1.2251x; 1.2251x over previous
#include <cuda_runtime.h>
#include <cstdint>
#include <cstddef>

// ---------------------------------------------------------------------------
// PolicyHead round 3:
//   prep   : W1/W2/W3 -> tf32 bits, k-dim permuted (fragment-pair friendly)
//   gemm1  : out = relu(x@W1^T+b1)            cp.async 2-stage, tile 128x128
//   gemm23 : q = out@W2^T+b2 ; k = out@W3^T+b3 (shared A tile), tile 128x128
//   att    : logits/promo/gather per 64-block, cp.async 4-chunk pipeline
// out/q/k stored as permuted tf32 bit patterns -> zero cvt in gemm23/att,
// all B (and most A) fragments load as LDS.64.
// ---------------------------------------------------------------------------

#define HDIM 256
#define MROWS 262144
#define PSCALE 0.0625f

__device__ unsigned g_out[(size_t)MROWS * HDIM];
__device__ unsigned g_q[(size_t)MROWS * HDIM];
__device__ unsigned g_k[(size_t)MROWS * HDIM];
__device__ unsigned g_w[3 * HDIM * HDIM];

__device__ __forceinline__ unsigned f2tf(float f) {
    unsigned r;
    asm("cvt.rna.tf32.f32 %0, %1;" : "=r"(r) : "f"(f));
    return r;
}

// k-dim permutation: values at (ks+t) and (ks+t+4) become adjacent words.
__device__ __forceinline__ int perm(int c) {
    return (c & ~7) | ((c & 3) << 1) | ((c >> 2) & 1);
}

__device__ __forceinline__ void mma8(float* d, const unsigned* a, const unsigned* b) {
    asm volatile(
        "mma.sync.aligned.m16n8k8.row.col.f32.tf32.tf32.f32 "
        "{%0,%1,%2,%3}, {%4,%5,%6,%7}, {%8,%9}, {%0,%1,%2,%3};\n"
        : "+f"(d[0]), "+f"(d[1]), "+f"(d[2]), "+f"(d[3])
        : "r"(a[0]), "r"(a[1]), "r"(a[2]), "r"(a[3]), "r"(b[0]), "r"(b[1]));
}

__device__ __forceinline__ unsigned sptr(const void* p) {
    return (unsigned)__cvta_generic_to_shared(p);
}
__device__ __forceinline__ void cpa16(unsigned s, const void* g) {
    asm volatile("cp.async.ca.shared.global [%0], [%1], 16;" :: "r"(s), "l"(g));
}
#define CPA_COMMIT asm volatile("cp.async.commit_group;")
#define CPA_WAIT(n) asm volatile("cp.async.wait_group %0;" :: "n"(n))

// ---------------------------------------------------------------------------
__global__ void prep_kernel(const float* __restrict__ w1, const float* __restrict__ w2,
                            const float* __restrict__ w3) {
    int i = blockIdx.x * 256 + threadIdx.x;           // 0..65535
    int row = i >> 8, col = i & 255;
    int d = row * HDIM + perm(col);
    g_w[d]                     = f2tf(w1[i]);
    g_w[HDIM * HDIM + d]       = f2tf(w2[i]);
    g_w[2 * HDIM * HDIM + d]   = f2tf(w3[i]);
}

// ---------------------------------------------------------------------------
// GEMM1: out = relu(x @ W1^T + b1). 256 thr, tile 128x128, BK=32, 2-stage.
// A raw f32 (cvt at fragment time), B pre-tf32 permuted (LDS.64 frags).
// ---------------------------------------------------------------------------
constexpr int GS = 36;  // smem stride words (36%32==4 -> conflict-free frags)

__global__ __launch_bounds__(256)
void gemm1_kernel(const float* __restrict__ A, const unsigned* __restrict__ W,
                  const float* __restrict__ bias, unsigned* __restrict__ C) {
    extern __shared__ unsigned sh[];
    unsigned* sA = sh;                    // 2 * 128*GS
    unsigned* sB = sh + 2 * 128 * GS;     // 2 * 128*GS
    const int m0 = blockIdx.y * 128, n0 = blockIdx.x * 128;
    const int tid = threadIdx.x;
    const int warp = tid >> 5, lane = tid & 31, g = lane >> 2, t = lane & 3;
    const int wm = warp >> 1, wn = warp & 1;      // warp tile 32x64

    float acc[2][8][4];
#pragma unroll
    for (int i = 0; i < 2; i++)
#pragma unroll
        for (int j = 0; j < 8; j++)
#pragma unroll
            for (int l = 0; l < 4; l++) acc[i][j][l] = 0.f;

    const int lrow = tid >> 3, lc4 = (tid & 7) << 2;

    // stage 0
#pragma unroll
    for (int i = 0; i < 4; i++) {
        int row = lrow + i * 32;
        cpa16(sptr(&sA[row * GS + lc4]), A + (size_t)(m0 + row) * HDIM + lc4);
        cpa16(sptr(&sB[row * GS + lc4]), W + (size_t)(n0 + row) * HDIM + lc4);
    }
    CPA_COMMIT;

    for (int c = 0; c < 8; c++) {
        int cur = c & 1;
        if (c < 7) {
            int nx = cur ^ 1, k0 = (c + 1) * 32;
#pragma unroll
            for (int i = 0; i < 4; i++) {
                int row = lrow + i * 32;
                cpa16(sptr(&sA[nx * 128 * GS + row * GS + lc4]),
                      A + (size_t)(m0 + row) * HDIM + k0 + lc4);
                cpa16(sptr(&sB[nx * 128 * GS + row * GS + lc4]),
                      W + (size_t)(n0 + row) * HDIM + k0 + lc4);
            }
            CPA_COMMIT;
            CPA_WAIT(1);
        } else {
            CPA_WAIT(0);
        }
        __syncthreads();
        const unsigned* As = &sA[cur * 128 * GS];
        const unsigned* Bs = &sB[cur * 128 * GS];
#pragma unroll
        for (int ks = 0; ks < 32; ks += 8) {
            unsigned a[2][4];
#pragma unroll
            for (int mi = 0; mi < 2; mi++) {
                int r = wm * 32 + mi * 16;
                a[mi][0] = f2tf(__uint_as_float(As[(r + g) * GS + ks + t]));
                a[mi][1] = f2tf(__uint_as_float(As[(r + g + 8) * GS + ks + t]));
                a[mi][2] = f2tf(__uint_as_float(As[(r + g) * GS + ks + t + 4]));
                a[mi][3] = f2tf(__uint_as_float(As[(r + g + 8) * GS + ks + t + 4]));
            }
#pragma unroll
            for (int ni = 0; ni < 8; ni++) {
                int cc = wn * 64 + ni * 8;
                uint2 bv = *(const uint2*)&Bs[(cc + g) * GS + ks + 2 * t];
                unsigned bb[2] = {bv.x, bv.y};
                mma8(acc[0][ni], a[0], bb);
                mma8(acc[1][ni], a[1], bb);
            }
        }
        __syncthreads();
    }
#pragma unroll
    for (int mi = 0; mi < 2; mi++)
#pragma unroll
        for (int h = 0; h < 2; h++) {
            int r = m0 + wm * 32 + mi * 16 + g + h * 8;
#pragma unroll
            for (int ni = 0; ni < 8; ni++) {
                int cc = n0 + wn * 64 + ni * 8 + 2 * t;
                float v0 = fmaxf(acc[mi][ni][h * 2 + 0] + bias[cc], 0.f);
                float v1 = fmaxf(acc[mi][ni][h * 2 + 1] + bias[cc + 1], 0.f);
                C[(size_t)r * HDIM + perm(cc)]     = f2tf(v0);
                C[(size_t)r * HDIM + perm(cc + 1)] = f2tf(v1);
            }
        }
}

// ---------------------------------------------------------------------------
// GEMM23: q/k from shared A tile. 512 thr, tile 128x128, BK=32, 2-stage.
// Everything pre-tf32 + permuted: zero cvt, LDS.64 fragments.
// ---------------------------------------------------------------------------
__global__ __launch_bounds__(512)
void gemm23_kernel(const unsigned* __restrict__ A,
                   const unsigned* __restrict__ W2, const float* __restrict__ b2v,
                   const unsigned* __restrict__ W3, const float* __restrict__ b3v,
                   unsigned* __restrict__ Q, unsigned* __restrict__ K) {
    extern __shared__ unsigned sh[];
    unsigned* sA = sh;                     // 2*128*GS
    unsigned* s2 = sh + 2 * 128 * GS;
    unsigned* s3 = sh + 4 * 128 * GS;
    const int m0 = blockIdx.y * 128, n0 = blockIdx.x * 128;
    const int tid = threadIdx.x;
    const int warp = tid >> 5, lane = tid & 31, g = lane >> 2, t = lane & 3;
    const int wm = warp >> 1, wn = warp & 1;       // 16 warps: warp tile 16x64

    float aq[8][4], ak[8][4];
#pragma unroll
    for (int j = 0; j < 8; j++)
#pragma unroll
        for (int l = 0; l < 4; l++) { aq[j][l] = 0.f; ak[j][l] = 0.f; }

    const int lrow = tid >> 3, lc4 = (tid & 7) << 2;   // rows 0..63 per i-step

#pragma unroll
    for (int i = 0; i < 2; i++) {
        int row = lrow + i * 64;
        cpa16(sptr(&sA[row * GS + lc4]), A + (size_t)(m0 + row) * HDIM + lc4);
        cpa16(sptr(&s2[row * GS + lc4]), W2 + (size_t)(n0 + row) * HDIM + lc4);
        cpa16(sptr(&s3[row * GS + lc4]), W3 + (size_t)(n0 + row) * HDIM + lc4);
    }
    CPA_COMMIT;

    for (int c = 0; c < 8; c++) {
        int cur = c & 1;
        if (c < 7) {
            int nx = cur ^ 1, k0 = (c + 1) * 32;
#pragma unroll
            for (int i = 0; i < 2; i++) {
                int row = lrow + i * 64;
                cpa16(sptr(&sA[nx * 128 * GS + row * GS + lc4]),
                      A + (size_t)(m0 + row) * HDIM + k0 + lc4);
                cpa16(sptr(&s2[nx * 128 * GS + row * GS + lc4]),
                      W2 + (size_t)(n0 + row) * HDIM + k0 + lc4);
                cpa16(sptr(&s3[nx * 128 * GS + row * GS + lc4]),
                      W3 + (size_t)(n0 + row) * HDIM + k0 + lc4);
            }
            CPA_COMMIT;
            CPA_WAIT(1);
        } else {
            CPA_WAIT(0);
        }
        __syncthreads();
        const unsigned* As = &sA[cur * 128 * GS];
        const unsigned* B2 = &s2[cur * 128 * GS];
        const unsigned* B3 = &s3[cur * 128 * GS];
#pragma unroll
        for (int ks = 0; ks < 32; ks += 8) {
            int r = wm * 16;
            uint2 a0 = *(const uint2*)&As[(r + g) * GS + ks + 2 * t];
            uint2 a1 = *(const uint2*)&As[(r + g + 8) * GS + ks + 2 * t];
            unsigned a[4] = {a0.x, a1.x, a0.y, a1.y};
#pragma unroll
            for (int ni = 0; ni < 8; ni++) {
                int cc = wn * 64 + ni * 8;
                uint2 bq = *(const uint2*)&B2[(cc + g) * GS + ks + 2 * t];
                uint2 bk = *(const uint2*)&B3[(cc + g) * GS + ks + 2 * t];
                unsigned bbq[2] = {bq.x, bq.y};
                unsigned bbk[2] = {bk.x, bk.y};
                mma8(aq[ni], a, bbq);
                mma8(ak[ni], a, bbk);
            }
        }
        __syncthreads();
    }
    // epilogue
#pragma unroll
    for (int ni = 0; ni < 8; ni++) {
        int cg = n0 + wn * 64 + ni * 8 + 2 * t;
        int p0 = perm(cg), p1 = perm(cg + 1);
        float bq0 = b2v[cg], bq1 = b2v[cg + 1];
        float bk0 = b3v[cg], bk1 = b3v[cg + 1];
        size_t r0 = (size_t)(m0 + wm * 16 + g) * HDIM;
        size_t r8 = r0 + 8 * HDIM;
        Q[r0 + p0] = f2tf(aq[ni][0] + bq0);
        Q[r0 + p1] = f2tf(aq[ni][1] + bq1);
        Q[r8 + p0] = f2tf(aq[ni][2] + bq0);
        Q[r8 + p1] = f2tf(aq[ni][3] + bq1);
        K[r0 + p0] = f2tf(ak[ni][0] + bk0);
        K[r0 + p1] = f2tf(ak[ni][1] + bk1);
        K[r8 + p0] = f2tf(ak[ni][2] + bk0);
        K[r8 + p1] = f2tf(ak[ni][3] + bk1);
    }
}

// ---------------------------------------------------------------------------
// Attention + promo + gather. 512 thr, one CTA per 64-row block.
// q/k arrive as permuted tf32 bits; cp.async 4-chunk pipeline.
// ---------------------------------------------------------------------------
constexpr int ASTR = 260;

__global__ __launch_bounds__(512)
void att_kernel(const unsigned* __restrict__ Qg, const unsigned* __restrict__ Kg,
                const float* __restrict__ w4, const int* __restrict__ gidx,
                float* __restrict__ out) {
    extern __shared__ unsigned sh[];
    unsigned* qs  = sh;                       // 64*260
    unsigned* kss = sh + 64 * ASTR;           // 64*260
    float* fulls  = (float*)(sh + 2 * 64 * ASTR);   // 4288
    float* offs   = fulls + 4288;             // 32

    const int b = blockIdx.x, tid = threadIdx.x;
    const unsigned* qb = Qg + (size_t)b * 64 * HDIM;
    const unsigned* kb = Kg + (size_t)b * 64 * HDIM;

    // issue all 4 column-chunk groups up front
#pragma unroll
    for (int c = 0; c < 4; c++) {
#pragma unroll
        for (int i = 0; i < 2; i++) {
            int id = tid + i * 512;               // 0..1023 per tile-chunk
            int row = id >> 4, c4 = (id & 15) << 2;
            cpa16(sptr(&qs[row * ASTR + c * 64 + c4]), qb + row * HDIM + c * 64 + c4);
            cpa16(sptr(&kss[row * ASTR + c * 64 + c4]), kb + row * HDIM + c * 64 + c4);
        }
        CPA_COMMIT;
    }

    const int warp = tid >> 5, lane = tid & 31, g = lane >> 2, t = lane & 3;
    const int wm = warp >> 2, wn = warp & 3;   // 4x4 warps, warp tile 16x16

    float acc[2][4];
#pragma unroll
    for (int i = 0; i < 2; i++)
#pragma unroll
        for (int j = 0; j < 4; j++) acc[i][j] = 0.f;

    auto chunk = [&](int c) {
#pragma unroll
        for (int k8 = c * 64; k8 < c * 64 + 64; k8 += 8) {
            int r = wm * 16;
            uint2 a0 = *(const uint2*)&qs[(r + g) * ASTR + k8 + 2 * t];
            uint2 a1 = *(const uint2*)&qs[(r + g + 8) * ASTR + k8 + 2 * t];
            unsigned a[4] = {a0.x, a1.x, a0.y, a1.y};
#pragma unroll
            for (int ni = 0; ni < 2; ni++) {
                int cc = wn * 16 + ni * 8;
                uint2 bv = *(const uint2*)&kss[(cc + g) * ASTR + k8 + 2 * t];
                unsigned bb[2] = {bv.x, bv.y};
                mma8(acc[ni], a, bb);
            }
        }
    };
    CPA_WAIT(3); __syncthreads(); chunk(0);
    CPA_WAIT(2); __syncthreads(); chunk(1);
    CPA_WAIT(1); __syncthreads(); chunk(2);
    CPA_WAIT(0); __syncthreads(); chunk(3);

#pragma unroll
    for (int ni = 0; ni < 2; ni++) {
        int cc = wn * 16 + ni * 8 + 2 * t;
        int r0 = wm * 16 + g;
        fulls[r0 * 64 + cc]           = acc[ni][0] * PSCALE;
        fulls[r0 * 64 + cc + 1]       = acc[ni][1] * PSCALE;
        fulls[(r0 + 8) * 64 + cc]     = acc[ni][2] * PSCALE;
        fulls[(r0 + 8) * 64 + cc + 1] = acc[ni][3] * PSCALE;
    }
    __syncthreads();

    // promo offs: 32 dot-products, 8 lanes each + shfl reduce
    if (tid < 256) {
        int pair = tid >> 3, l = tid & 7;
        int p = pair >> 3, s = pair & 7;
        const unsigned* kr = &kss[(56 + s) * ASTR];
        const float* w4r = w4 + p * HDIM;
        float sum = 0.f;
#pragma unroll
        for (int j = 0; j < 32; j++) {
            int pp = l + 8 * j;                             // physical (permuted) idx
            int kk = (pp & ~7) | ((pp & 1) << 2) | ((pp >> 1) & 3);  // logical idx
            sum += __uint_as_float(kr[pp]) * w4r[kk];
        }
        sum += __shfl_down_sync(0xffffffffu, sum, 4);
        sum += __shfl_down_sync(0xffffffffu, sum, 2);
        sum += __shfl_down_sync(0xffffffffu, sum, 1);
        if (l == 0) offs[pair] = sum;
    }
    __syncthreads();

    if (tid < 192) {
        int qq = tid / 24, rr = tid % 24, s = rr / 3, p = rr % 3;
        fulls[4096 + tid] = offs[p * 8 + s] + offs[24 + s]
                          + fulls[(48 + qq) * 64 + 56 + s];
    }
    __syncthreads();

    float* ob = out + (size_t)b * 1858;
    for (int i = tid; i < 1858; i += 512) ob[i] = fulls[gidx[i]];
}

// ---------------------------------------------------------------------------
extern "C" void kernel_launch(void* const* d_in, const int* in_sizes, int n_in,
                              void* d_out, int out_size) {
    const float* x  = (const float*)d_in[0];
    const float* w1 = (const float*)d_in[1];
    const float* b1 = (const float*)d_in[2];
    const float* w2 = (const float*)d_in[3];
    const float* b2 = (const float*)d_in[4];
    const float* w3 = (const float*)d_in[5];
    const float* b3 = (const float*)d_in[6];
    const float* w4 = (const float*)d_in[7];
    const int*   gi = (const int*)d_in[8];
    float* out = (float*)d_out;

    const int M = in_sizes[0] / HDIM;     // 262144
    const int nblk = M / 64;              // 4096

    unsigned *o, *q, *k, *w;
    cudaGetSymbolAddress((void**)&o, g_out);
    cudaGetSymbolAddress((void**)&q, g_q);
    cudaGetSymbolAddress((void**)&k, g_k);
    cudaGetSymbolAddress((void**)&w, g_w);

    const int smem1  = 4 * 128 * GS * 4;                     // 73728
    const int smem23 = 6 * 128 * GS * 4;                     // 110592
    const int smemA  = (2 * 64 * ASTR + 4288 + 32) * 4;      // 150400

    static bool init = false;
    if (!init) {
        cudaFuncSetAttribute((const void*)gemm1_kernel,
                             cudaFuncAttributeMaxDynamicSharedMemorySize, smem1);
        cudaFuncSetAttribute((const void*)gemm23_kernel,
                             cudaFuncAttributeMaxDynamicSharedMemorySize, smem23);
        cudaFuncSetAttribute((const void*)att_kernel,
                             cudaFuncAttributeMaxDynamicSharedMemorySize, smemA);
        init = true;
    }

    prep_kernel<<<HDIM * HDIM / 256, 256>>>(w1, w2, w3);
    gemm1_kernel<<<dim3(2, M / 128), 256, smem1>>>(x, w, b1, o);
    gemm23_kernel<<<dim3(2, M / 128), 512, smem23>>>(o, w + HDIM * HDIM, b2,
                                                     w + 2 * HDIM * HDIM, b3, q, k);
    att_kernel<<<nblk, 512, smemA>>>(q, k, w4, gi, out);
}

// round 5
// speedup vs baseline: 1.5357x; 1.2535x over previous
#include <cuda_runtime.h>
#include <cstdint>
#include <cstddef>

// ---------------------------------------------------------------------------
// PolicyHead round 4: algebraic fusion.
//   logits = out@M@out^T + u.out_i + v.out_j + s0,  M = W2^T W3 (precomputed)
//   offs[p][s] = out_{56+s} . wp[p] + d0[p],        wp = W3^T w4_p
// Kernels: prep_w1, prepM, prepv, gemm1 (out=relu(x@W1^T+b1)), attf (fused).
// q/k never exist; out read once. All tf32 mma with permuted-k LDS.64 frags.
// ---------------------------------------------------------------------------

#define HDIM 256
#define MROWS 262144
#define PSCALE 0.0625f

__device__ unsigned g_out[(size_t)MROWS * HDIM];
__device__ unsigned g_w1[HDIM * HDIM];
__device__ unsigned g_mt[HDIM * HDIM];     // Mt[c,a] = M[a,c], tf32, perm(a)
__device__ float    g_u[HDIM];             // perm-indexed
__device__ float    g_v[HDIM];             // perm-indexed
__device__ float    g_wp[4 * HDIM];        // perm-indexed
__device__ float    g_misc[8];             // [0]=s0, [1..4]=d0[p]

__device__ __forceinline__ unsigned f2tf(float f) {
    unsigned r;
    asm("cvt.rna.tf32.f32 %0, %1;" : "=r"(r) : "f"(f));
    return r;
}
__device__ __forceinline__ int perm(int c) {
    return (c & ~7) | ((c & 3) << 1) | ((c >> 2) & 1);
}
__device__ __forceinline__ void mma8(float* d, const unsigned* a, const unsigned* b) {
    asm volatile(
        "mma.sync.aligned.m16n8k8.row.col.f32.tf32.tf32.f32 "
        "{%0,%1,%2,%3}, {%4,%5,%6,%7}, {%8,%9}, {%0,%1,%2,%3};\n"
        : "+f"(d[0]), "+f"(d[1]), "+f"(d[2]), "+f"(d[3])
        : "r"(a[0]), "r"(a[1]), "r"(a[2]), "r"(a[3]), "r"(b[0]), "r"(b[1]));
}
__device__ __forceinline__ unsigned sptr(const void* p) {
    return (unsigned)__cvta_generic_to_shared(p);
}
__device__ __forceinline__ void cpa16(unsigned s, const void* g) {
    asm volatile("cp.async.ca.shared.global [%0], [%1], 16;" :: "r"(s), "l"(g));
}
#define CPA_COMMIT asm volatile("cp.async.commit_group;")
#define CPA_WAIT(n) asm volatile("cp.async.wait_group %0;" :: "n"(n))

// ---------------------------------------------------------------------------
__global__ void prep_w1_kernel(const float* __restrict__ w1) {
    int i = blockIdx.x * 256 + threadIdx.x;
    int row = i >> 8, col = i & 255;
    g_w1[row * HDIM + perm(col)] = f2tf(w1[i]);
}

// Mt tile 64x64 per CTA, grid 16. Mt[c,a] = sum_h W2[h,a] W3[h,c], fp32 accum.
__global__ __launch_bounds__(256)
void prepM_kernel(const float* __restrict__ w2, const float* __restrict__ w3) {
    extern __shared__ float s[];
    float* s2 = s;               // [256][68] cols a0..a0+63
    float* s3 = s + 256 * 68;    // [256][68] cols c0..c0+63
    const int a0 = (blockIdx.x & 3) * 64, c0 = (blockIdx.x >> 2) * 64;
    const int tid = threadIdx.x;
    for (int j = tid; j < 256 * 16; j += 256) {
        int h = j >> 4, q4 = (j & 15) << 2;
        *(float4*)&s2[h * 68 + q4] = *(const float4*)(w2 + h * HDIM + a0 + q4);
        *(float4*)&s3[h * 68 + q4] = *(const float4*)(w3 + h * HDIM + c0 + q4);
    }
    __syncthreads();
    const int tx = tid & 15, ty = tid >> 4;
    float acc[4][4] = {};
    for (int h = 0; h < 256; h++) {
        float4 av = *(float4*)&s2[h * 68 + tx * 4];
        float4 cv = *(float4*)&s3[h * 68 + ty * 4];
        float aa[4] = {av.x, av.y, av.z, av.w};
        float cc[4] = {cv.x, cv.y, cv.z, cv.w};
#pragma unroll
        for (int i = 0; i < 4; i++)
#pragma unroll
            for (int j = 0; j < 4; j++) acc[i][j] += cc[i] * aa[j];
    }
#pragma unroll
    for (int i = 0; i < 4; i++)
#pragma unroll
        for (int j = 0; j < 4; j++)
            g_mt[(c0 + ty * 4 + i) * HDIM + perm(a0 + tx * 4 + j)] = f2tf(acc[i][j]);
}

__global__ void prepv_kernel(const float* __restrict__ w2, const float* __restrict__ b2,
                             const float* __restrict__ w3, const float* __restrict__ b3,
                             const float* __restrict__ w4) {
    int a = threadIdx.x;
    float u = 0.f, v = 0.f, p0 = 0.f, p1 = 0.f, p2 = 0.f, p3 = 0.f;
    for (int h = 0; h < 256; h++) {
        float w2v = w2[h * HDIM + a], w3v = w3[h * HDIM + a];
        u += w2v * b3[h];
        v += b2[h] * w3v;
        p0 += w3v * w4[0 * HDIM + h];
        p1 += w3v * w4[1 * HDIM + h];
        p2 += w3v * w4[2 * HDIM + h];
        p3 += w3v * w4[3 * HDIM + h];
    }
    int pa = perm(a);
    g_u[pa] = u; g_v[pa] = v;
    g_wp[0 * HDIM + pa] = p0; g_wp[1 * HDIM + pa] = p1;
    g_wp[2 * HDIM + pa] = p2; g_wp[3 * HDIM + pa] = p3;
    if (a == 0) {
        float s = 0.f;
        for (int h = 0; h < 256; h++) s += b2[h] * b3[h];
        g_misc[0] = s;
    }
    if (a >= 1 && a <= 4) {
        float d = 0.f;
        for (int h = 0; h < 256; h++) d += b3[h] * w4[(a - 1) * HDIM + h];
        g_misc[a] = d;
    }
}

// ---------------------------------------------------------------------------
// GEMM1: out = relu(x @ W1^T + b1). 256 thr, tile 128x128, BK=32, 2-stage.
// ---------------------------------------------------------------------------
constexpr int GS = 36;

__global__ __launch_bounds__(256)
void gemm1_kernel(const float* __restrict__ A, const float* __restrict__ bias,
                  unsigned* __restrict__ C) {
    extern __shared__ unsigned sh[];
    unsigned* sA = sh;
    unsigned* sB = sh + 2 * 128 * GS;
    const int m0 = blockIdx.y * 128, n0 = blockIdx.x * 128;
    const int tid = threadIdx.x;
    const int warp = tid >> 5, lane = tid & 31, g = lane >> 2, t = lane & 3;
    const int wm = warp >> 1, wn = warp & 1;

    float acc[2][8][4];
#pragma unroll
    for (int i = 0; i < 2; i++)
#pragma unroll
        for (int j = 0; j < 8; j++)
#pragma unroll
            for (int l = 0; l < 4; l++) acc[i][j][l] = 0.f;

    const int lrow = tid >> 3, lc4 = (tid & 7) << 2;

#pragma unroll
    for (int i = 0; i < 4; i++) {
        int row = lrow + i * 32;
        cpa16(sptr(&sA[row * GS + lc4]), A + (size_t)(m0 + row) * HDIM + lc4);
        cpa16(sptr(&sB[row * GS + lc4]), g_w1 + (size_t)(n0 + row) * HDIM + lc4);
    }
    CPA_COMMIT;

    for (int c = 0; c < 8; c++) {
        int cur = c & 1;
        if (c < 7) {
            int nx = cur ^ 1, k0 = (c + 1) * 32;
#pragma unroll
            for (int i = 0; i < 4; i++) {
                int row = lrow + i * 32;
                cpa16(sptr(&sA[nx * 128 * GS + row * GS + lc4]),
                      A + (size_t)(m0 + row) * HDIM + k0 + lc4);
                cpa16(sptr(&sB[nx * 128 * GS + row * GS + lc4]),
                      g_w1 + (size_t)(n0 + row) * HDIM + k0 + lc4);
            }
            CPA_COMMIT;
            CPA_WAIT(1);
        } else {
            CPA_WAIT(0);
        }
        __syncthreads();
        const unsigned* As = &sA[cur * 128 * GS];
        const unsigned* Bs = &sB[cur * 128 * GS];
#pragma unroll
        for (int ks = 0; ks < 32; ks += 8) {
            unsigned a[2][4];
#pragma unroll
            for (int mi = 0; mi < 2; mi++) {
                int r = wm * 32 + mi * 16;
                a[mi][0] = f2tf(__uint_as_float(As[(r + g) * GS + ks + t]));
                a[mi][1] = f2tf(__uint_as_float(As[(r + g + 8) * GS + ks + t]));
                a[mi][2] = f2tf(__uint_as_float(As[(r + g) * GS + ks + t + 4]));
                a[mi][3] = f2tf(__uint_as_float(As[(r + g + 8) * GS + ks + t + 4]));
            }
#pragma unroll
            for (int ni = 0; ni < 8; ni++) {
                int cc = wn * 64 + ni * 8;
                uint2 bv = *(const uint2*)&Bs[(cc + g) * GS + ks + 2 * t];
                unsigned bb[2] = {bv.x, bv.y};
                mma8(acc[0][ni], a[0], bb);
                mma8(acc[1][ni], a[1], bb);
            }
        }
        __syncthreads();
    }
#pragma unroll
    for (int mi = 0; mi < 2; mi++)
#pragma unroll
        for (int h = 0; h < 2; h++) {
            int r = m0 + wm * 32 + mi * 16 + g + h * 8;
#pragma unroll
            for (int ni = 0; ni < 8; ni++) {
                int cc = n0 + wn * 64 + ni * 8 + 2 * t;
                float v0 = fmaxf(acc[mi][ni][h * 2 + 0] + bias[cc], 0.f);
                float v1 = fmaxf(acc[mi][ni][h * 2 + 1] + bias[cc + 1], 0.f);
                C[(size_t)r * HDIM + perm(cc)]     = f2tf(v0);
                C[(size_t)r * HDIM + perm(cc + 1)] = f2tf(v1);
            }
        }
}

// ---------------------------------------------------------------------------
// Fused: tmp = out_b @ Mt^T; logits = (tmp@out^T + uo_i + vo_j + s0)*SCALE;
// promo; gather. 256 thr (8 warps), one CTA per 64-row block.
// ---------------------------------------------------------------------------
constexpr int OS = 260;   // outs/tmp stride (words)
constexpr int MS = 36;    // M-chunk stride
constexpr int SM_TMP  = 64 * OS;
constexpr int SM_M    = 2 * 64 * OS;
constexpr int SM_MISC = SM_M + 2 * 256 * MS;
constexpr int SMA_WORDS = SM_MISC + 160;   // uo64+vo64+offs32

__global__ __launch_bounds__(256)
void attf_kernel(const int* __restrict__ gidx, float* __restrict__ out) {
    extern __shared__ unsigned sh[];
    unsigned* outs = sh;
    unsigned* tmp  = sh + SM_TMP;
    unsigned* sM   = sh + SM_M;
    float* uo   = (float*)(sh + SM_MISC);
    float* vo   = uo + 64;
    float* offs = vo + 64;
    float* fulls = (float*)sM;    // alias: sM dead after phase 1

    const int b = blockIdx.x, tid = threadIdx.x;
    const unsigned* ob = g_out + (size_t)b * 64 * HDIM;

    // group0: outs (64x256) + M chunk0 (256x32)
#pragma unroll
    for (int i = 0; i < 16; i++) {
        int idx = tid + i * 256;
        int row = idx >> 6, c4 = (idx & 63) << 2;
        cpa16(sptr(&outs[row * OS + c4]), ob + row * HDIM + c4);
    }
#pragma unroll
    for (int i = 0; i < 8; i++) {
        int idx = tid + i * 256;
        int row = idx >> 3, c4 = (idx & 7) << 2;
        cpa16(sptr(&sM[row * MS + c4]), g_mt + row * HDIM + c4);
    }
    CPA_COMMIT;

    const int warp = tid >> 5, lane = tid & 31, g = lane >> 2, t = lane & 3;
    const int wm = warp >> 2, wn = warp & 3;   // phase1: 2x4 warps, tile 32x64

    float acc[2][8][4];
#pragma unroll
    for (int i = 0; i < 2; i++)
#pragma unroll
        for (int j = 0; j < 8; j++)
#pragma unroll
            for (int l = 0; l < 4; l++) acc[i][j][l] = 0.f;

    for (int c = 0; c < 8; c++) {
        int cur = c & 1;
        if (c < 7) {
            int nx = cur ^ 1, k0 = (c + 1) * 32;
#pragma unroll
            for (int i = 0; i < 8; i++) {
                int idx = tid + i * 256;
                int row = idx >> 3, c4 = (idx & 7) << 2;
                cpa16(sptr(&sM[nx * 256 * MS + row * MS + c4]),
                      g_mt + row * HDIM + k0 + c4);
            }
            CPA_COMMIT;
            CPA_WAIT(1);
        } else {
            CPA_WAIT(0);
        }
        __syncthreads();
        const unsigned* Ms = &sM[cur * 256 * MS];
        const unsigned* As = &outs[c * 32];
#pragma unroll
        for (int ks = 0; ks < 32; ks += 8) {
            unsigned a[2][4];
#pragma unroll
            for (int mi = 0; mi < 2; mi++) {
                int r = wm * 32 + mi * 16;
                uint2 a0 = *(const uint2*)&As[(r + g) * OS + ks + 2 * t];
                uint2 a1 = *(const uint2*)&As[(r + g + 8) * OS + ks + 2 * t];
                a[mi][0] = a0.x; a[mi][1] = a1.x; a[mi][2] = a0.y; a[mi][3] = a1.y;
            }
#pragma unroll
            for (int ni = 0; ni < 8; ni++) {
                int cc = wn * 64 + ni * 8;
                uint2 bv = *(const uint2*)&Ms[(cc + g) * MS + ks + 2 * t];
                unsigned bb[2] = {bv.x, bv.y};
                mma8(acc[0][ni], a[0], bb);
                mma8(acc[1][ni], a[1], bb);
            }
        }
        __syncthreads();
    }

    // phase-1 epilogue: tmp (tf32 bits, permuted cols)
#pragma unroll
    for (int mi = 0; mi < 2; mi++)
#pragma unroll
        for (int ni = 0; ni < 8; ni++) {
            int cc = wn * 64 + ni * 8 + 2 * t;
            int p0 = perm(cc), p1 = perm(cc + 1);
            int r = wm * 32 + mi * 16 + g;
            tmp[r * OS + p0]       = f2tf(acc[mi][ni][0]);
            tmp[r * OS + p1]       = f2tf(acc[mi][ni][1]);
            tmp[(r + 8) * OS + p0] = f2tf(acc[mi][ni][2]);
            tmp[(r + 8) * OS + p1] = f2tf(acc[mi][ni][3]);
        }
    __syncthreads();

    // uo[i] = u.out_i ; vo[i] = v.out_i  (4 lanes per row)
    {
        int i = tid >> 2, part = tid & 3;
        const unsigned* orow = &outs[i * OS];
        float su = 0.f, sv = 0.f;
#pragma unroll 8
        for (int j = 0; j < 64; j++) {
            int pp = part * 64 + j;
            float ov = __uint_as_float(orow[pp]);
            su += g_u[pp] * ov;
            sv += g_v[pp] * ov;
        }
        su += __shfl_down_sync(0xffffffffu, su, 2);
        su += __shfl_down_sync(0xffffffffu, su, 1);
        sv += __shfl_down_sync(0xffffffffu, sv, 2);
        sv += __shfl_down_sync(0xffffffffu, sv, 1);
        if (part == 0) { uo[i] = su; vo[i] = sv; }
    }
    // offs[p*8+s] = out_{56+s} . wp[p] + d0[p]  (8 lanes per pair)
    {
        int pair = tid >> 3, l = tid & 7, p = pair >> 3, s = pair & 7;
        const unsigned* kr = &outs[(56 + s) * OS];
        const float* wr = g_wp + p * HDIM;
        float sum = 0.f;
#pragma unroll 8
        for (int j = 0; j < 32; j++) {
            int pp = l + 8 * j;
            sum += __uint_as_float(kr[pp]) * wr[pp];
        }
        sum += __shfl_down_sync(0xffffffffu, sum, 4);
        sum += __shfl_down_sync(0xffffffffu, sum, 2);
        sum += __shfl_down_sync(0xffffffffu, sum, 1);
        if (l == 0) offs[pair] = sum + g_misc[1 + p];
    }

    // phase 2: logits = tmp @ outs^T. 2x4 warps, warp tile 32x16.
    float acc2[2][2][4];
#pragma unroll
    for (int i = 0; i < 2; i++)
#pragma unroll
        for (int j = 0; j < 2; j++)
#pragma unroll
            for (int l = 0; l < 4; l++) acc2[i][j][l] = 0.f;

    for (int k8 = 0; k8 < HDIM; k8 += 8) {
        unsigned a[2][4];
#pragma unroll
        for (int mi = 0; mi < 2; mi++) {
            int r = wm * 32 + mi * 16;
            uint2 a0 = *(const uint2*)&tmp[(r + g) * OS + k8 + 2 * t];
            uint2 a1 = *(const uint2*)&tmp[(r + g + 8) * OS + k8 + 2 * t];
            a[mi][0] = a0.x; a[mi][1] = a1.x; a[mi][2] = a0.y; a[mi][3] = a1.y;
        }
#pragma unroll
        for (int ni = 0; ni < 2; ni++) {
            int cc = wn * 16 + ni * 8;
            uint2 bv = *(const uint2*)&outs[(cc + g) * OS + k8 + 2 * t];
            unsigned bb[2] = {bv.x, bv.y};
            mma8(acc2[0][ni], a[0], bb);
            mma8(acc2[1][ni], a[1], bb);
        }
    }
    __syncthreads();   // uo/vo/offs visible; phase-1 sM reads long done

    const float s0v = g_misc[0];
#pragma unroll
    for (int mi = 0; mi < 2; mi++)
#pragma unroll
        for (int ni = 0; ni < 2; ni++) {
            int cc = wn * 16 + ni * 8 + 2 * t;
            int r = wm * 32 + mi * 16 + g;
            fulls[r * 64 + cc]           = (acc2[mi][ni][0] + uo[r] + vo[cc] + s0v) * PSCALE;
            fulls[r * 64 + cc + 1]       = (acc2[mi][ni][1] + uo[r] + vo[cc + 1] + s0v) * PSCALE;
            fulls[(r + 8) * 64 + cc]     = (acc2[mi][ni][2] + uo[r + 8] + vo[cc] + s0v) * PSCALE;
            fulls[(r + 8) * 64 + cc + 1] = (acc2[mi][ni][3] + uo[r + 8] + vo[cc + 1] + s0v) * PSCALE;
        }
    __syncthreads();

    if (tid < 192) {
        int qq = tid / 24, rr = tid % 24, s = rr / 3, p = rr % 3;
        fulls[4096 + tid] = offs[p * 8 + s] + offs[24 + s]
                          + fulls[(48 + qq) * 64 + 56 + s];
    }
    __syncthreads();

    float* obp = out + (size_t)b * 1858;
    for (int i = tid; i < 1858; i += 256) obp[i] = fulls[gidx[i]];
}

// ---------------------------------------------------------------------------
extern "C" void kernel_launch(void* const* d_in, const int* in_sizes, int n_in,
                              void* d_out, int out_size) {
    const float* x  = (const float*)d_in[0];
    const float* w1 = (const float*)d_in[1];
    const float* b1 = (const float*)d_in[2];
    const float* w2 = (const float*)d_in[3];
    const float* b2 = (const float*)d_in[4];
    const float* w3 = (const float*)d_in[5];
    const float* b3 = (const float*)d_in[6];
    const float* w4 = (const float*)d_in[7];
    const int*   gi = (const int*)d_in[8];
    float* out = (float*)d_out;

    const int M = in_sizes[0] / HDIM;     // 262144
    const int nblk = M / 64;              // 4096

    unsigned* o;
    cudaGetSymbolAddress((void**)&o, g_out);

    const int smemM = 2 * 256 * 68 * 4;        // 139264
    const int smem1 = 4 * 128 * GS * 4;        // 73728
    const int smemA = SMA_WORDS * 4;           // 207488

    static bool init = false;
    if (!init) {
        cudaFuncSetAttribute((const void*)prepM_kernel,
                             cudaFuncAttributeMaxDynamicSharedMemorySize, smemM);
        cudaFuncSetAttribute((const void*)gemm1_kernel,
                             cudaFuncAttributeMaxDynamicSharedMemorySize, smem1);
        cudaFuncSetAttribute((const void*)attf_kernel,
                             cudaFuncAttributeMaxDynamicSharedMemorySize, smemA);
        init = true;
    }

    prep_w1_kernel<<<HDIM * HDIM / 256, 256>>>(w1);
    prepM_kernel<<<16, 256, smemM>>>(w2, w3);
    prepv_kernel<<<1, 256>>>(w2, b2, w3, b3, w4);
    gemm1_kernel<<<dim3(2, M / 128), 256, smem1>>>(x, b1, o);
    attf_kernel<<<nblk, 256, smemA>>>(gi, out);
}

// round 6
// speedup vs baseline: 1.9167x; 1.2481x over previous
#include <cuda_runtime.h>
#include <cstdint>
#include <cstddef>

// ---------------------------------------------------------------------------
// PolicyHead round 5:
//   logits = out@M@out^T + u.out_i + v.out_j + s0,  M = W2^T W3 (precomputed)
//   attf: nc-chunked (64-col chunks of tmp), 107KB smem -> 2 CTAs/SM.
//   Bank-conflict fix: uint2 fragment buffers use stride == 8 (mod 32).
// ---------------------------------------------------------------------------

#define HDIM 256
#define MROWS 262144
#define PSCALE 0.0625f

__device__ unsigned g_out[(size_t)MROWS * HDIM];
__device__ unsigned g_w1[HDIM * HDIM];
__device__ unsigned g_mt[HDIM * HDIM];     // Mt[c,a] = M[a,c], tf32, perm(a)
__device__ float    g_u[HDIM];             // perm-indexed
__device__ float    g_v[HDIM];             // perm-indexed
__device__ float    g_wp[4 * HDIM];        // perm-indexed
__device__ float    g_misc[8];             // [0]=s0, [1..4]=d0[p]

__device__ __forceinline__ unsigned f2tf(float f) {
    unsigned r;
    asm("cvt.rna.tf32.f32 %0, %1;" : "=r"(r) : "f"(f));
    return r;
}
__device__ __forceinline__ int perm(int c) {
    return (c & ~7) | ((c & 3) << 1) | ((c >> 2) & 1);
}
__device__ __forceinline__ void mma8(float* d, const unsigned* a, const unsigned* b) {
    asm volatile(
        "mma.sync.aligned.m16n8k8.row.col.f32.tf32.tf32.f32 "
        "{%0,%1,%2,%3}, {%4,%5,%6,%7}, {%8,%9}, {%0,%1,%2,%3};\n"
        : "+f"(d[0]), "+f"(d[1]), "+f"(d[2]), "+f"(d[3])
        : "r"(a[0]), "r"(a[1]), "r"(a[2]), "r"(a[3]), "r"(b[0]), "r"(b[1]));
}
__device__ __forceinline__ unsigned sptr(const void* p) {
    return (unsigned)__cvta_generic_to_shared(p);
}
__device__ __forceinline__ void cpa16(unsigned s, const void* g) {
    asm volatile("cp.async.ca.shared.global [%0], [%1], 16;" :: "r"(s), "l"(g));
}
#define CPA_COMMIT asm volatile("cp.async.commit_group;")
#define CPA_WAIT(n) asm volatile("cp.async.wait_group %0;" :: "n"(n))

// ---------------------------------------------------------------------------
__global__ void prep_w1_kernel(const float* __restrict__ w1) {
    int i = blockIdx.x * 256 + threadIdx.x;
    int row = i >> 8, col = i & 255;
    g_w1[row * HDIM + perm(col)] = f2tf(w1[i]);
}

// Mt tile 64x64 per CTA, grid 16. Mt[c,a] = sum_h W2[h,a] W3[h,c], fp32 accum.
__global__ __launch_bounds__(256)
void prepM_kernel(const float* __restrict__ w2, const float* __restrict__ w3) {
    extern __shared__ float s[];
    float* s2 = s;               // [256][68]
    float* s3 = s + 256 * 68;
    const int a0 = (blockIdx.x & 3) * 64, c0 = (blockIdx.x >> 2) * 64;
    const int tid = threadIdx.x;
    for (int j = tid; j < 256 * 16; j += 256) {
        int h = j >> 4, q4 = (j & 15) << 2;
        *(float4*)&s2[h * 68 + q4] = *(const float4*)(w2 + h * HDIM + a0 + q4);
        *(float4*)&s3[h * 68 + q4] = *(const float4*)(w3 + h * HDIM + c0 + q4);
    }
    __syncthreads();
    const int tx = tid & 15, ty = tid >> 4;
    float acc[4][4] = {};
    for (int h = 0; h < 256; h++) {
        float4 av = *(float4*)&s2[h * 68 + tx * 4];
        float4 cv = *(float4*)&s3[h * 68 + ty * 4];
        float aa[4] = {av.x, av.y, av.z, av.w};
        float cc[4] = {cv.x, cv.y, cv.z, cv.w};
#pragma unroll
        for (int i = 0; i < 4; i++)
#pragma unroll
            for (int j = 0; j < 4; j++) acc[i][j] += cc[i] * aa[j];
    }
#pragma unroll
    for (int i = 0; i < 4; i++)
#pragma unroll
        for (int j = 0; j < 4; j++)
            g_mt[(c0 + ty * 4 + i) * HDIM + perm(a0 + tx * 4 + j)] = f2tf(acc[i][j]);
}

__global__ void prepv_kernel(const float* __restrict__ w2, const float* __restrict__ b2,
                             const float* __restrict__ w3, const float* __restrict__ b3,
                             const float* __restrict__ w4) {
    int a = threadIdx.x;
    float u = 0.f, v = 0.f, p0 = 0.f, p1 = 0.f, p2 = 0.f, p3 = 0.f;
    for (int h = 0; h < 256; h++) {
        float w2v = w2[h * HDIM + a], w3v = w3[h * HDIM + a];
        u += w2v * b3[h];
        v += b2[h] * w3v;
        p0 += w3v * w4[0 * HDIM + h];
        p1 += w3v * w4[1 * HDIM + h];
        p2 += w3v * w4[2 * HDIM + h];
        p3 += w3v * w4[3 * HDIM + h];
    }
    int pa = perm(a);
    g_u[pa] = u; g_v[pa] = v;
    g_wp[0 * HDIM + pa] = p0; g_wp[1 * HDIM + pa] = p1;
    g_wp[2 * HDIM + pa] = p2; g_wp[3 * HDIM + pa] = p3;
    if (a == 0) {
        float s = 0.f;
        for (int h = 0; h < 256; h++) s += b2[h] * b3[h];
        g_misc[0] = s;
    }
    if (a >= 1 && a <= 4) {
        float d = 0.f;
        for (int h = 0; h < 256; h++) d += b3[h] * w4[(a - 1) * HDIM + h];
        g_misc[a] = d;
    }
}

// ---------------------------------------------------------------------------
// GEMM1: out = relu(x @ W1^T + b1). 256 thr, tile 128x128, BK=32, 2-stage.
// sA stride 36 (LDS.32 frags, ==4 mod 32); sB stride 40 (LDS.64 frags, ==8).
// ---------------------------------------------------------------------------
constexpr int GSA = 36;
constexpr int GSB = 40;

__global__ __launch_bounds__(256, 2)
void gemm1_kernel(const float* __restrict__ A, const float* __restrict__ bias,
                  unsigned* __restrict__ C) {
    extern __shared__ unsigned sh[];
    unsigned* sA = sh;                      // 2*128*GSA
    unsigned* sB = sh + 2 * 128 * GSA;      // 2*128*GSB
    const int m0 = blockIdx.y * 128, n0 = blockIdx.x * 128;
    const int tid = threadIdx.x;
    const int warp = tid >> 5, lane = tid & 31, g = lane >> 2, t = lane & 3;
    const int wm = warp >> 1, wn = warp & 1;

    float acc[2][8][4];
#pragma unroll
    for (int i = 0; i < 2; i++)
#pragma unroll
        for (int j = 0; j < 8; j++)
#pragma unroll
            for (int l = 0; l < 4; l++) acc[i][j][l] = 0.f;

    const int lrow = tid >> 3, lc4 = (tid & 7) << 2;

#pragma unroll
    for (int i = 0; i < 4; i++) {
        int row = lrow + i * 32;
        cpa16(sptr(&sA[row * GSA + lc4]), A + (size_t)(m0 + row) * HDIM + lc4);
        cpa16(sptr(&sB[row * GSB + lc4]), g_w1 + (size_t)(n0 + row) * HDIM + lc4);
    }
    CPA_COMMIT;

    for (int c = 0; c < 8; c++) {
        int cur = c & 1;
        if (c < 7) {
            int nx = cur ^ 1, k0 = (c + 1) * 32;
#pragma unroll
            for (int i = 0; i < 4; i++) {
                int row = lrow + i * 32;
                cpa16(sptr(&sA[nx * 128 * GSA + row * GSA + lc4]),
                      A + (size_t)(m0 + row) * HDIM + k0 + lc4);
                cpa16(sptr(&sB[nx * 128 * GSB + row * GSB + lc4]),
                      g_w1 + (size_t)(n0 + row) * HDIM + k0 + lc4);
            }
            CPA_COMMIT;
            CPA_WAIT(1);
        } else {
            CPA_WAIT(0);
        }
        __syncthreads();
        const unsigned* As = &sA[cur * 128 * GSA];
        const unsigned* Bs = &sB[cur * 128 * GSB];
#pragma unroll
        for (int ks = 0; ks < 32; ks += 8) {
            unsigned a[2][4];
#pragma unroll
            for (int mi = 0; mi < 2; mi++) {
                int r = wm * 32 + mi * 16;
                a[mi][0] = f2tf(__uint_as_float(As[(r + g) * GSA + ks + t]));
                a[mi][1] = f2tf(__uint_as_float(As[(r + g + 8) * GSA + ks + t]));
                a[mi][2] = f2tf(__uint_as_float(As[(r + g) * GSA + ks + t + 4]));
                a[mi][3] = f2tf(__uint_as_float(As[(r + g + 8) * GSA + ks + t + 4]));
            }
#pragma unroll
            for (int ni = 0; ni < 8; ni++) {
                int cc = wn * 64 + ni * 8;
                uint2 bv = *(const uint2*)&Bs[(cc + g) * GSB + ks + 2 * t];
                unsigned bb[2] = {bv.x, bv.y};
                mma8(acc[0][ni], a[0], bb);
                mma8(acc[1][ni], a[1], bb);
            }
        }
        __syncthreads();
    }
#pragma unroll
    for (int mi = 0; mi < 2; mi++)
#pragma unroll
        for (int h = 0; h < 2; h++) {
            int r = m0 + wm * 32 + mi * 16 + g + h * 8;
#pragma unroll
            for (int ni = 0; ni < 8; ni++) {
                int cc = n0 + wn * 64 + ni * 8 + 2 * t;
                float v0 = fmaxf(acc[mi][ni][h * 2 + 0] + bias[cc], 0.f);
                float v1 = fmaxf(acc[mi][ni][h * 2 + 1] + bias[cc + 1], 0.f);
                C[(size_t)r * HDIM + perm(cc)]     = f2tf(v0);
                C[(size_t)r * HDIM + perm(cc + 1)] = f2tf(v1);
            }
        }
}

// ---------------------------------------------------------------------------
// attf v2: nc-chunked. One CTA (256 thr) per 64-row block; 2 CTAs/SM.
// For nc = 0..3: tmpc[64x64] = outs @ Mt[nc*64..+64]^T (Mt double-buffered
// in 64x32 tiles), then logits += tmpc @ outs[:,nc*64..+64]^T (registers).
// Strides: outs 264, mt 40, tmpc 72 (all == 8 mod 32 -> conflict-free uint2).
// ---------------------------------------------------------------------------
constexpr int OS2 = 264;
constexpr int MTS = 40;
constexpr int TPS = 72;
constexpr int SM2_MT    = 64 * OS2;               // 16896
constexpr int SM2_TMPC  = SM2_MT + 2 * 64 * MTS;  // 22016
constexpr int SM2_MISC  = SM2_TMPC + 64 * TPS;    // 26624
constexpr int SM2_WORDS = SM2_MISC + 160;         // 26784

__global__ __launch_bounds__(256, 2)
void attf_kernel(const int* __restrict__ gidx, float* __restrict__ out) {
    extern __shared__ unsigned sh[];
    unsigned* outs = sh;
    unsigned* mt   = sh + SM2_MT;
    unsigned* tmpc = sh + SM2_TMPC;
    float* uo   = (float*)(sh + SM2_MISC);
    float* vo   = uo + 64;
    float* offs = vo + 64;
    float* fulls = (float*)sh;     // alias outs (dead after uo/vo/offs)

    const int b = blockIdx.x, tid = threadIdx.x;
    const unsigned* ob = g_out + (size_t)b * 64 * HDIM;

    // outs (64x256) + Mt tile 0 -> group 0
#pragma unroll
    for (int i = 0; i < 16; i++) {
        int idx = tid + i * 256;
        int row = idx >> 6, c4 = (idx & 63) << 2;
        cpa16(sptr(&outs[row * OS2 + c4]), ob + row * HDIM + c4);
    }
#pragma unroll
    for (int i = 0; i < 2; i++) {
        int e = tid + i * 256;
        int r = e >> 3, c4 = (e & 7) << 2;
        cpa16(sptr(&mt[r * MTS + c4]), g_mt + (size_t)r * HDIM + c4);
    }
    CPA_COMMIT;

    const int warp = tid >> 5, lane = tid & 31, g = lane >> 2, t = lane & 3;
    const int wm = warp >> 1, wn = warp & 1;   // warp tile 16(m) x 32(n)

    float acc2[4][4];                           // persistent logits partials
#pragma unroll
    for (int i = 0; i < 4; i++)
#pragma unroll
        for (int j = 0; j < 4; j++) acc2[i][j] = 0.f;

    for (int nc = 0; nc < 4; nc++) {
        float acc[4][4];
#pragma unroll
        for (int i = 0; i < 4; i++)
#pragma unroll
            for (int j = 0; j < 4; j++) acc[i][j] = 0.f;

        for (int kc = 0; kc < 8; kc++) {
            int tt = nc * 8 + kc;
            int cur = tt & 1;
            if (tt < 31) {
                int nn = tt + 1;
                int nrow0 = (nn >> 3) * 64, ncol0 = (nn & 7) * 32;
#pragma unroll
                for (int i = 0; i < 2; i++) {
                    int e = tid + i * 256;
                    int r = e >> 3, c4 = (e & 7) << 2;
                    cpa16(sptr(&mt[(cur ^ 1) * 64 * MTS + r * MTS + c4]),
                          g_mt + (size_t)(nrow0 + r) * HDIM + ncol0 + c4);
                }
                CPA_COMMIT;
                CPA_WAIT(1);
            } else {
                CPA_WAIT(0);
            }
            __syncthreads();
            const unsigned* mb = &mt[cur * 64 * MTS];
            const int kb = kc * 32;
#pragma unroll
            for (int ks = 0; ks < 32; ks += 8) {
                uint2 a0 = *(const uint2*)&outs[(wm * 16 + g) * OS2 + kb + ks + 2 * t];
                uint2 a1 = *(const uint2*)&outs[(wm * 16 + g + 8) * OS2 + kb + ks + 2 * t];
                unsigned a[4] = {a0.x, a1.x, a0.y, a1.y};
#pragma unroll
                for (int ni = 0; ni < 4; ni++) {
                    int c = wn * 32 + ni * 8;
                    uint2 bv = *(const uint2*)&mb[(c + g) * MTS + ks + 2 * t];
                    unsigned bb[2] = {bv.x, bv.y};
                    mma8(acc[ni], a, bb);
                }
            }
            __syncthreads();
        }
        // tmpc (perm within chunk, tf32)
#pragma unroll
        for (int ni = 0; ni < 4; ni++) {
            int cc = wn * 32 + ni * 8 + 2 * t;
            int p0 = perm(cc), p1 = perm(cc + 1);
            int r = wm * 16 + g;
            tmpc[r * TPS + p0]       = f2tf(acc[ni][0]);
            tmpc[r * TPS + p1]       = f2tf(acc[ni][1]);
            tmpc[(r + 8) * TPS + p0] = f2tf(acc[ni][2]);
            tmpc[(r + 8) * TPS + p1] = f2tf(acc[ni][3]);
        }
        __syncthreads();
        // logits += tmpc @ outs_cols(nc)^T
#pragma unroll
        for (int k8 = 0; k8 < 64; k8 += 8) {
            uint2 a0 = *(const uint2*)&tmpc[(wm * 16 + g) * TPS + k8 + 2 * t];
            uint2 a1 = *(const uint2*)&tmpc[(wm * 16 + g + 8) * TPS + k8 + 2 * t];
            unsigned a[4] = {a0.x, a1.x, a0.y, a1.y};
#pragma unroll
            for (int ni = 0; ni < 4; ni++) {
                int c = wn * 32 + ni * 8;
                uint2 bv = *(const uint2*)&outs[(c + g) * OS2 + nc * 64 + k8 + 2 * t];
                unsigned bb[2] = {bv.x, bv.y};
                mma8(acc2[ni], a, bb);
            }
        }
        __syncthreads();
    }

    // uo[i] = u.out_i ; vo[i] = v.out_i
    {
        int i = tid >> 2, part = tid & 3;
        const unsigned* orow = &outs[i * OS2];
        float su = 0.f, sv = 0.f;
#pragma unroll 8
        for (int j = 0; j < 64; j++) {
            int pp = part * 64 + j;
            float ov = __uint_as_float(orow[pp]);
            su += g_u[pp] * ov;
            sv += g_v[pp] * ov;
        }
        su += __shfl_down_sync(0xffffffffu, su, 2);
        su += __shfl_down_sync(0xffffffffu, su, 1);
        sv += __shfl_down_sync(0xffffffffu, sv, 2);
        sv += __shfl_down_sync(0xffffffffu, sv, 1);
        if (part == 0) { uo[i] = su; vo[i] = sv; }
    }
    // offs[p*8+s] = out_{56+s} . wp[p] + d0[p]
    {
        int pair = tid >> 3, l = tid & 7, p = pair >> 3, s = pair & 7;
        const unsigned* kr = &outs[(56 + s) * OS2];
        const float* wr = g_wp + p * HDIM;
        float sum = 0.f;
#pragma unroll 8
        for (int j = 0; j < 32; j++) {
            int pp = l + 8 * j;
            sum += __uint_as_float(kr[pp]) * wr[pp];
        }
        sum += __shfl_down_sync(0xffffffffu, sum, 4);
        sum += __shfl_down_sync(0xffffffffu, sum, 2);
        sum += __shfl_down_sync(0xffffffffu, sum, 1);
        if (l == 0) offs[pair] = sum + g_misc[1 + p];
    }
    __syncthreads();   // outs reads done -> fulls may overwrite

    const float s0v = g_misc[0];
#pragma unroll
    for (int ni = 0; ni < 4; ni++) {
        int cc = wn * 32 + ni * 8 + 2 * t;
        int r = wm * 16 + g;
        fulls[r * 64 + cc]           = (acc2[ni][0] + uo[r] + vo[cc] + s0v) * PSCALE;
        fulls[r * 64 + cc + 1]       = (acc2[ni][1] + uo[r] + vo[cc + 1] + s0v) * PSCALE;
        fulls[(r + 8) * 64 + cc]     = (acc2[ni][2] + uo[r + 8] + vo[cc] + s0v) * PSCALE;
        fulls[(r + 8) * 64 + cc + 1] = (acc2[ni][3] + uo[r + 8] + vo[cc + 1] + s0v) * PSCALE;
    }
    __syncthreads();

    if (tid < 192) {
        int qq = tid / 24, rr = tid % 24, s = rr / 3, p = rr % 3;
        fulls[4096 + tid] = offs[p * 8 + s] + offs[24 + s]
                          + fulls[(48 + qq) * 64 + 56 + s];
    }
    __syncthreads();

    float* obp = out + (size_t)b * 1858;
    for (int i = tid; i < 1858; i += 256) obp[i] = fulls[gidx[i]];
}

// ---------------------------------------------------------------------------
extern "C" void kernel_launch(void* const* d_in, const int* in_sizes, int n_in,
                              void* d_out, int out_size) {
    const float* x  = (const float*)d_in[0];
    const float* w1 = (const float*)d_in[1];
    const float* b1 = (const float*)d_in[2];
    const float* w2 = (const float*)d_in[3];
    const float* b2 = (const float*)d_in[4];
    const float* w3 = (const float*)d_in[5];
    const float* b3 = (const float*)d_in[6];
    const float* w4 = (const float*)d_in[7];
    const int*   gi = (const int*)d_in[8];
    float* out = (float*)d_out;

    const int M = in_sizes[0] / HDIM;     // 262144
    const int nblk = M / 64;              // 4096

    unsigned* o;
    cudaGetSymbolAddress((void**)&o, g_out);

    const int smemM = 2 * 256 * 68 * 4;                        // 139264
    const int smem1 = (2 * 128 * GSA + 2 * 128 * GSB) * 4;     // 77824
    const int smemA = SM2_WORDS * 4;                           // 107136

    static bool init = false;
    if (!init) {
        cudaFuncSetAttribute((const void*)prepM_kernel,
                             cudaFuncAttributeMaxDynamicSharedMemorySize, smemM);
        cudaFuncSetAttribute((const void*)gemm1_kernel,
                             cudaFuncAttributeMaxDynamicSharedMemorySize, smem1);
        cudaFuncSetAttribute((const void*)attf_kernel,
                             cudaFuncAttributeMaxDynamicSharedMemorySize, smemA);
        init = true;
    }

    prep_w1_kernel<<<HDIM * HDIM / 256, 256>>>(w1);
    prepM_kernel<<<16, 256, smemM>>>(w2, w3);
    prepv_kernel<<<1, 256>>>(w2, b2, w3, b3, w4);
    gemm1_kernel<<<dim3(2, M / 128), 256, smem1>>>(x, b1, o);
    attf_kernel<<<nblk, 256, smemA>>>(gi, out);
}